// round 4
// baseline (speedup 1.0000x reference)
#include <cuda_runtime.h>

namespace {
constexpr int NN   = 24;   // nodes
constexpr int FIN  = 7;    // input features
constexpr int WD   = 64;   // hidden width
constexpr int FOUT = 13;   // output features
constexpr int TB   = 16;   // batch tile per CTA
constexpr int HB   = 4;    // batch rows per thread (TB/4)
constexpr int NT   = 768;  // 24 nodes * 4 batch-quarters * 8 o-groups
constexpr int STATE = NN * WD;  // 1536 floats per batch row
}

// SMPL tree adjacency (self + parent + children), CSR in constant memory.
__constant__ int c_nbr_off[25] = {0,4,7,10,13,16,19,22,25,28,33,35,37,40,43,46,48,51,54,57,60,63,66,68,70};
__constant__ int c_nbr_lst[70] = {
    0,1,2,3,
    1,0,4,
    2,0,5,
    3,0,6,
    4,1,7,
    5,2,8,
    6,3,9,
    7,4,10,
    8,5,11,
    9,6,12,13,14,
    10,7,
    11,8,
    12,9,15,
    13,9,16,
    14,9,17,
    15,12,
    16,13,18,
    17,14,19,
    18,16,20,
    19,17,21,
    20,18,22,
    21,19,23,
    22,20,
    23,21
};
__constant__ int c_nbr_m[70] = {
    0,0,0,0,
    1,1,1,
    2,2,2,
    3,3,3,
    4,4,4,
    5,5,5,
    6,6,6,
    7,7,7,
    8,8,8,
    9,9,9,9,9,
    10,10,
    11,11,
    12,12,12,
    13,13,13,
    14,14,14,
    15,15,
    16,16,16,
    17,17,17,
    18,18,18,
    19,19,19,
    20,20,20,
    21,21,21,
    22,22,
    23,23
};

#define FMA8(AL, AH, S, WL, WH)                 \
    do {                                        \
        AL.x = fmaf((S), (WL).x, AL.x);         \
        AL.y = fmaf((S), (WL).y, AL.y);         \
        AL.z = fmaf((S), (WL).z, AL.z);         \
        AL.w = fmaf((S), (WL).w, AL.w);         \
        AH.x = fmaf((S), (WH).x, AH.x);         \
        AH.y = fmaf((S), (WH).y, AH.y);         \
        AH.z = fmaf((S), (WH).z, AH.z);         \
        AH.w = fmaf((S), (WH).w, AH.w);         \
    } while (0)

__global__ __launch_bounds__(NT, 1)
void gnn_fused(const float* __restrict__ x,
               const float* __restrict__ w0, const float* __restrict__ w1,
               const float* __restrict__ w2, const float* __restrict__ w3,
               const float* __restrict__ aw0, const float* __restrict__ aw1,
               const float* __restrict__ aw2, const float* __restrict__ aw3,
               const float* __restrict__ b0, const float* __restrict__ b1,
               const float* __restrict__ b2, const float* __restrict__ b3,
               float* __restrict__ out)
{
    extern __shared__ float smem[];
    float* bufA = smem;                    // TB*STATE floats
    float* bufB = bufA + TB * STATE;       // TB*STATE
    float* xin  = bufB;                    // alias: xin dead once L0 agg writes bufB
    float* aeff = bufB + TB * STATE;       // 4*70 masked adjacency weights
    float* bias = aeff + 4 * 70;           // 3*64 + 13

    const int tid = threadIdx.x;
    const long brow0 = (long)blockIdx.x * TB;

    // Stage masked adjacency weights (adjw * adj, nonzeros only)
    for (int idx = tid; idx < 4 * 70; idx += NT) {
        int l = idx / 70, e = idx - l * 70;
        const float* aw = (l == 0) ? aw0 : (l == 1) ? aw1 : (l == 2) ? aw2 : aw3;
        aeff[idx] = aw[c_nbr_m[e] * NN + c_nbr_lst[e]];
    }
    // Stage biases
    for (int idx = tid; idx < 3 * WD + FOUT; idx += NT) {
        float v;
        if      (idx <     WD) v = b0[idx];
        else if (idx < 2 * WD) v = b1[idx - WD];
        else if (idx < 3 * WD) v = b2[idx - 2 * WD];
        else                   v = b3[idx - 3 * WD];
        bias[idx] = v;
    }
    // Stage input tile with root-node mask (node 0 zeroed)
    for (int idx = tid; idx < TB * NN * FIN; idx += NT) {
        int j = idx % (NN * FIN);
        float v = x[brow0 * (NN * FIN) + idx];
        if (j < FIN) v = 0.0f;  // root joint masked
        xin[idx] = v;
    }
    __syncthreads();

    // Thread map: warp = one node. 32 lanes = 4 batch-quarters x 8 o-groups.
    // Quarters share weight addresses -> 4x warp-level LDG dedup.
    const int n  = tid >> 5;              // node 0..23
    const int bq = (tid & 31) >> 3;       // batch quarter 0..3
    const int og = tid & 7;               // output group 0..7
    const int o0 = og * 8;                // 8 outputs per thread
    const int bb = bq * HB;               // first batch row

    // ---- Layer 0 matmul: xin[b][n][0:7] @ w0[n][7][64] -> bufA ----
    {
        float4 accL[HB], accH[HB];
        #pragma unroll
        for (int b = 0; b < HB; b++) {
            accL[b] = make_float4(0.f, 0.f, 0.f, 0.f);
            accH[b] = make_float4(0.f, 0.f, 0.f, 0.f);
        }
        #pragma unroll
        for (int i = 0; i < FIN; i++) {
            const float4 wL = __ldg(reinterpret_cast<const float4*>(w0 + (n * FIN + i) * WD + o0));
            const float4 wH = __ldg(reinterpret_cast<const float4*>(w0 + (n * FIN + i) * WD + o0 + 4));
            #pragma unroll
            for (int b = 0; b < HB; b++) {
                const float xv = xin[(bb + b) * (NN * FIN) + n * FIN + i];
                FMA8(accL[b], accH[b], xv, wL, wH);
            }
        }
        #pragma unroll
        for (int b = 0; b < HB; b++) {
            *reinterpret_cast<float4*>(bufA + (bb + b) * STATE + n * WD + o0) = accL[b];
            *reinterpret_cast<float4*>(bufA + (bb + b) * STATE + n * WD + o0 + 4) = accH[b];
        }
    }
    __syncthreads();

    // Sparse tree aggregation + bias (+ReLU): h -> dst
    auto agg = [&](const float* __restrict__ h, const float* __restrict__ ae,
                   const float* __restrict__ bi, float* __restrict__ dst, bool relu) {
        const int s = c_nbr_off[n], e = c_nbr_off[n + 1];
        const float4 bvL = *reinterpret_cast<const float4*>(bi + o0);
        const float4 bvH = *reinterpret_cast<const float4*>(bi + o0 + 4);
        #pragma unroll
        for (int b = 0; b < HB; b++) {
            float4 aL = bvL, aH = bvH;
            for (int k = s; k < e; k++) {
                const float aw = ae[k];
                const float* hp = h + (bb + b) * STATE + c_nbr_lst[k] * WD + o0;
                const float4 hL = *reinterpret_cast<const float4*>(hp);
                const float4 hH = *reinterpret_cast<const float4*>(hp + 4);
                FMA8(aL, aH, aw, hL, hH);
            }
            if (relu) {
                aL.x = fmaxf(aL.x, 0.f); aL.y = fmaxf(aL.y, 0.f);
                aL.z = fmaxf(aL.z, 0.f); aL.w = fmaxf(aL.w, 0.f);
                aH.x = fmaxf(aH.x, 0.f); aH.y = fmaxf(aH.y, 0.f);
                aH.z = fmaxf(aH.z, 0.f); aH.w = fmaxf(aH.w, 0.f);
            }
            float* dp = dst + (bb + b) * STATE + n * WD + o0;
            *reinterpret_cast<float4*>(dp) = aL;
            *reinterpret_cast<float4*>(dp + 4) = aH;
        }
    };

    // Hidden-layer per-node matmul: src[b][n][0:64] @ w[n][64][64] -> dst
    // i chunked by 4: one LDS.128 act per (b,chunk) feeding 32 FMAs.
    // Weights staged in two 16-reg sub-chunks to stay under the reg cap.
    auto mm64 = [&](const float* __restrict__ src, const float* __restrict__ wgt,
                    float* __restrict__ dst) {
        float4 accL[HB], accH[HB];
        #pragma unroll
        for (int b = 0; b < HB; b++) {
            accL[b] = make_float4(0.f, 0.f, 0.f, 0.f);
            accH[b] = make_float4(0.f, 0.f, 0.f, 0.f);
        }
        const float* wbase = wgt + n * WD * WD + o0;
        const float* abase = src + n * WD;
        #pragma unroll 2
        for (int i = 0; i < WD; i += 4) {
            float4 xv[HB];
            #pragma unroll
            for (int b = 0; b < HB; b++)
                xv[b] = *reinterpret_cast<const float4*>(abase + (bb + b) * STATE + i);
            // sub-chunk i, i+1
            {
                const float4 w0L = __ldg(reinterpret_cast<const float4*>(wbase + (i + 0) * WD));
                const float4 w0H = __ldg(reinterpret_cast<const float4*>(wbase + (i + 0) * WD + 4));
                const float4 w1L = __ldg(reinterpret_cast<const float4*>(wbase + (i + 1) * WD));
                const float4 w1H = __ldg(reinterpret_cast<const float4*>(wbase + (i + 1) * WD + 4));
                #pragma unroll
                for (int b = 0; b < HB; b++) {
                    FMA8(accL[b], accH[b], xv[b].x, w0L, w0H);
                    FMA8(accL[b], accH[b], xv[b].y, w1L, w1H);
                }
            }
            // sub-chunk i+2, i+3
            {
                const float4 w2L = __ldg(reinterpret_cast<const float4*>(wbase + (i + 2) * WD));
                const float4 w2H = __ldg(reinterpret_cast<const float4*>(wbase + (i + 2) * WD + 4));
                const float4 w3L = __ldg(reinterpret_cast<const float4*>(wbase + (i + 3) * WD));
                const float4 w3H = __ldg(reinterpret_cast<const float4*>(wbase + (i + 3) * WD + 4));
                #pragma unroll
                for (int b = 0; b < HB; b++) {
                    FMA8(accL[b], accH[b], xv[b].z, w2L, w2H);
                    FMA8(accL[b], accH[b], xv[b].w, w3L, w3H);
                }
            }
        }
        #pragma unroll
        for (int b = 0; b < HB; b++) {
            float* dp = dst + (bb + b) * STATE + n * WD + o0;
            *reinterpret_cast<float4*>(dp) = accL[b];
            *reinterpret_cast<float4*>(dp + 4) = accH[b];
        }
    };

    agg(bufA, aeff + 0, bias + 0, bufB, true);        // L0 agg
    __syncthreads();
    mm64(bufB, w1, bufA);                              // L1 matmul
    __syncthreads();
    agg(bufA, aeff + 70, bias + WD, bufB, true);       // L1 agg
    __syncthreads();
    mm64(bufB, w2, bufA);                              // L2 matmul
    __syncthreads();
    agg(bufA, aeff + 140, bias + 2 * WD, bufB, true);  // L2 agg
    __syncthreads();

    // ---- Layer 3 matmul: bufB[b][n][0:64] @ w3[n][64][13] -> bufA (stride WD) ----
    if (tid < NN * FOUT) {
        const int n3 = tid / FOUT, o3 = tid - n3 * FOUT;
        float acc[TB];
        #pragma unroll
        for (int b = 0; b < TB; b++) acc[b] = 0.f;
        #pragma unroll 4
        for (int i = 0; i < WD; i++) {
            const float wv = __ldg(w3 + (n3 * WD + i) * FOUT + o3);
            #pragma unroll
            for (int b = 0; b < TB; b++)
                acc[b] = fmaf(bufB[b * STATE + n3 * WD + i], wv, acc[b]);
        }
        #pragma unroll
        for (int b = 0; b < TB; b++)
            bufA[b * STATE + n3 * WD + o3] = acc[b];
    }
    __syncthreads();

    // ---- Layer 3 aggregation + bias, store to global ----
    if (tid < NN * FOUT) {
        const int n3 = tid / FOUT, o3 = tid - n3 * FOUT;
        const int s = c_nbr_off[n3], e = c_nbr_off[n3 + 1];
        const float bbv = bias[3 * WD + o3];
        #pragma unroll
        for (int b = 0; b < TB; b++) {
            float a0 = bbv;
            for (int k = s; k < e; k++)
                a0 = fmaf(aeff[210 + k], bufA[b * STATE + c_nbr_lst[k] * WD + o3], a0);
            out[(brow0 + b) * (NN * FOUT) + n3 * FOUT + o3] = a0;
        }
    }
}

extern "C" void kernel_launch(void* const* d_in, const int* in_sizes, int n_in,
                              void* d_out, int out_size) {
    const float* x   = (const float*)d_in[0];
    const float* w0  = (const float*)d_in[1];
    const float* w1  = (const float*)d_in[2];
    const float* w2  = (const float*)d_in[3];
    const float* w3  = (const float*)d_in[4];
    const float* aw0 = (const float*)d_in[5];
    const float* aw1 = (const float*)d_in[6];
    const float* aw2 = (const float*)d_in[7];
    const float* aw3 = (const float*)d_in[8];
    const float* b0  = (const float*)d_in[9];
    const float* b1  = (const float*)d_in[10];
    const float* b2  = (const float*)d_in[11];
    const float* b3  = (const float*)d_in[12];
    float* out = (float*)d_out;

    const int B = in_sizes[0] / (NN * FIN);
    const int grid = (B + TB - 1) / TB;
    const size_t smem_bytes =
        (size_t)(2 * TB * STATE + 4 * 70 + 3 * WD + FOUT) * sizeof(float);

    cudaFuncSetAttribute(gnn_fused, cudaFuncAttributeMaxDynamicSharedMemorySize,
                         (int)smem_bytes);
    gnn_fused<<<grid, NT, smem_bytes>>>(x, w0, w1, w2, w3,
                                        aw0, aw1, aw2, aw3,
                                        b0, b1, b2, b3, out);
}